// round 3
// baseline (speedup 1.0000x reference)
#include <cuda_runtime.h>
#include <math.h>

// ---------------- problem constants ----------------
#define Bb   4
#define Tt   8000
#define DIMN 512
#define Hh   8
#define DHd  64
#define Cc   200
#define NBb  40
#define Mm   (Bb*Tt)        // 32000
#define NJ   (Bb*NBb*Hh)    // 1280
#define SCALE 0.125f

// ---------------- scratch (device globals; no allocation allowed) ----------------
__device__ float g_xn [Mm*DIMN];
__device__ float g_q  [Mm*DIMN];
__device__ float g_kv [Mm*2*DIMN];
__device__ float g_rel[Cc*Cc*DHd];
__device__ float g_pos[(size_t)NJ*Cc*Cc];   // [j][c][r], scaled, compact
__device__ float g_att[Mm*DIMN];
__device__ float g_wq [DIMN*DIMN];
__device__ float g_wkv[DIMN*2*DIMN];
__device__ float g_wo [DIMN*DIMN];

__device__ __forceinline__ unsigned f2tf32(float f) {
    unsigned u; asm("cvt.rna.tf32.f32 %0, %1;" : "=r"(u) : "f"(f)); return u;
}
__device__ __forceinline__ float ftf(float f) { return __uint_as_float(f2tf32(f)); }

// ---------------- pre-round weights to tf32 bit-pattern ----------------
__global__ void round_kernel(const float* __restrict__ src, float* __restrict__ dst, int n4) {
    int i = blockIdx.x*256 + threadIdx.x;
    if (i < n4) {
        float4 v = ((const float4*)src)[i];
        uint4 o = make_uint4(f2tf32(v.x), f2tf32(v.y), f2tf32(v.z), f2tf32(v.w));
        ((uint4*)dst)[i] = o;
    }
}

// ---------------- LayerNorm: one block per row (stores tf32-rounded) ----------------
__global__ void ln_kernel(const float* __restrict__ x,
                          const float* __restrict__ g,
                          const float* __restrict__ bta) {
    int row = blockIdx.x;
    int t = threadIdx.x;
    float4 v = ((const float4*)(x + (size_t)row*DIMN))[t];
    float s  = v.x + v.y + v.z + v.w;
    float ss = v.x*v.x + v.y*v.y + v.z*v.z + v.w*v.w;
    #pragma unroll
    for (int o = 16; o; o >>= 1) {
        s  += __shfl_xor_sync(~0u, s,  o);
        ss += __shfl_xor_sync(~0u, ss, o);
    }
    __shared__ float rs[4], rss[4];
    int w = t >> 5;
    if ((t & 31) == 0) { rs[w] = s; rss[w] = ss; }
    __syncthreads();
    s  = rs[0]  + rs[1]  + rs[2]  + rs[3];
    ss = rss[0] + rss[1] + rss[2] + rss[3];
    float mu  = s  * (1.0f/DIMN);
    float var = ss * (1.0f/DIMN) - mu*mu;
    float inv = rsqrtf(var + 1e-5f);
    float4 gg = ((const float4*)g)[t];
    float4 bb = ((const float4*)bta)[t];
    uint4 o;
    o.x = f2tf32((v.x-mu)*inv*gg.x + bb.x);
    o.y = f2tf32((v.y-mu)*inv*gg.y + bb.y);
    o.z = f2tf32((v.z-mu)*inv*gg.z + bb.z);
    o.w = f2tf32((v.w-mu)*inv*gg.w + bb.w);
    ((uint4*)(g_xn + (size_t)row*DIMN))[t] = o;
}

// ---------------- rel gather ----------------
__global__ void gather_kernel(const int* __restrict__ dists,
                              const float* __restrict__ pe) {
    int idx = blockIdx.x*256 + threadIdx.x;
    if (idx < Cc*Cc*DHd) {
        int cr = idx >> 6, d = idx & 63;
        g_rel[idx] = pe[dists[cr]*DHd + d];
    }
}

// ---------------- mma helper ----------------
__device__ __forceinline__ void mma8(float* c, const unsigned* a, const unsigned* b) {
    asm volatile("mma.sync.aligned.m16n8k8.row.col.f32.tf32.tf32.f32 "
        "{%0,%1,%2,%3}, {%4,%5,%6,%7}, {%8,%9}, {%0,%1,%2,%3};"
        : "+f"(c[0]), "+f"(c[1]), "+f"(c[2]), "+f"(c[3])
        : "r"(a[0]), "r"(a[1]), "r"(a[2]), "r"(a[3]), "r"(b[0]), "r"(b[1]));
}

// ---------------- tf32 tensor-core GEMM (unchanged from round 2) ----------------
#define BM 128
#define BN 128
#define BK 16
#define AST 136

__global__ __launch_bounds__(256)
void gemm_tf32(const float* __restrict__ A, const float* __restrict__ W,
               const float* __restrict__ bias, float* __restrict__ out, int N) {
    __shared__ unsigned As[2][BK][AST];
    __shared__ unsigned Bs[2][BK][AST];
    int tid  = threadIdx.x;
    int lane = tid & 31, warp = tid >> 5;
    int wm = warp >> 2, wn = warp & 3;
    int m0 = blockIdx.y*BM, n0 = blockIdx.x*BN;

    int ar = tid >> 2;
    int ak = (tid & 3) * 4;
    int ag = tid & 3;
    int bk = tid >> 4;
    int bn = (tid & 15) * 4;

    const float* Aptr = A + (size_t)(m0 + ar)*DIMN + ak;
    const float* Wptr = W + (size_t)bk*N + n0 + bn;

    float acc[4][4][4];
    #pragma unroll
    for (int i=0;i<4;i++)
        #pragma unroll
        for (int j=0;j<4;j++)
            #pragma unroll
            for (int r=0;r<4;r++) acc[i][j][r]=0.f;

    {
        float4 a0v = *(const float4*)(Aptr);
        float4 a1v = *(const float4*)(Aptr + (size_t)64*DIMN);
        unsigned d0 = (unsigned)__cvta_generic_to_shared(&Bs[0][bk][bn]);
        unsigned d1 = (unsigned)__cvta_generic_to_shared(&Bs[0][bk][bn+64]);
        asm volatile("cp.async.cg.shared.global [%0], [%1], 16;" :: "r"(d0), "l"(Wptr));
        asm volatile("cp.async.cg.shared.global [%0], [%1], 16;" :: "r"(d1), "l"(Wptr+64));
        asm volatile("cp.async.commit_group;");
        int c0 = ar ^ (ag<<3), c1 = (ar+64) ^ (ag<<3);
        As[0][ak+0][c0]=__float_as_uint(a0v.x); As[0][ak+1][c0]=__float_as_uint(a0v.y);
        As[0][ak+2][c0]=__float_as_uint(a0v.z); As[0][ak+3][c0]=__float_as_uint(a0v.w);
        As[0][ak+0][c1]=__float_as_uint(a1v.x); As[0][ak+1][c1]=__float_as_uint(a1v.y);
        As[0][ak+2][c1]=__float_as_uint(a1v.z); As[0][ak+3][c1]=__float_as_uint(a1v.w);
        asm volatile("cp.async.wait_group 0;");
        __syncthreads();
    }

    int buf = 0;
    for (int k0 = BK; k0 <= DIMN; k0 += BK) {
        float4 a0v, a1v;
        if (k0 < DIMN) {
            a0v = *(const float4*)(Aptr + k0);
            a1v = *(const float4*)(Aptr + (size_t)64*DIMN + k0);
            unsigned d0 = (unsigned)__cvta_generic_to_shared(&Bs[buf^1][bk][bn]);
            unsigned d1 = (unsigned)__cvta_generic_to_shared(&Bs[buf^1][bk][bn+64]);
            const float* wp = Wptr + (size_t)k0*N;
            asm volatile("cp.async.cg.shared.global [%0], [%1], 16;" :: "r"(d0), "l"(wp));
            asm volatile("cp.async.cg.shared.global [%0], [%1], 16;" :: "r"(d1), "l"(wp+64));
            asm volatile("cp.async.commit_group;");
        }
        #pragma unroll
        for (int ks = 0; ks < 2; ks++) {
            unsigned af[4][4], bf[4][2];
            int kr = ks*8 + (lane & 3);
            int g0 = (2*ks) << 3, g1 = (2*ks+1) << 3;
            #pragma unroll
            for (int mt = 0; mt < 4; mt++) {
                int mb = wm*64 + mt*16 + (lane>>2);
                af[mt][0] = As[buf][kr  ][ mb    ^ g0];
                af[mt][1] = As[buf][kr  ][(mb+8) ^ g0];
                af[mt][2] = As[buf][kr+4][ mb    ^ g1];
                af[mt][3] = As[buf][kr+4][(mb+8) ^ g1];
            }
            #pragma unroll
            for (int nt = 0; nt < 4; nt++) {
                int nb = wn*32 + nt*8 + (lane>>2);
                bf[nt][0] = Bs[buf][kr  ][nb];
                bf[nt][1] = Bs[buf][kr+4][nb];
            }
            #pragma unroll
            for (int mt = 0; mt < 4; mt++)
                #pragma unroll
                for (int nt = 0; nt < 4; nt++)
                    mma8(acc[mt][nt], af[mt], bf[nt]);
        }
        if (k0 < DIMN) {
            int c0 = ar ^ (ag<<3), c1 = (ar+64) ^ (ag<<3);
            As[buf^1][ak+0][c0]=__float_as_uint(a0v.x); As[buf^1][ak+1][c0]=__float_as_uint(a0v.y);
            As[buf^1][ak+2][c0]=__float_as_uint(a0v.z); As[buf^1][ak+3][c0]=__float_as_uint(a0v.w);
            As[buf^1][ak+0][c1]=__float_as_uint(a1v.x); As[buf^1][ak+1][c1]=__float_as_uint(a1v.y);
            As[buf^1][ak+2][c1]=__float_as_uint(a1v.z); As[buf^1][ak+3][c1]=__float_as_uint(a1v.w);
            asm volatile("cp.async.wait_group 0;");
            __syncthreads();
            buf ^= 1;
        }
    }

    #pragma unroll
    for (int mt = 0; mt < 4; mt++) {
        int row = m0 + wm*64 + mt*16 + (lane>>2);
        #pragma unroll
        for (int nt = 0; nt < 4; nt++) {
            int col = n0 + wn*32 + nt*8 + (lane&3)*2;
            float bv0 = 0.f, bv1 = 0.f;
            if (bias) { bv0 = bias[col]; bv1 = bias[col+1]; }
            *(float2*)(out + (size_t)row*N + col) =
                make_float2(acc[mt][nt][0]+bv0, acc[mt][nt][1]+bv1);
            *(float2*)(out + (size_t)(row+8)*N + col) =
                make_float2(acc[mt][nt][2]+bv0, acc[mt][nt][3]+bv1);
        }
    }
}

// ---------------- pos bias: P[j][c][r] = SCALE * rel[c] @ q_c  (compact stride 200) ----
__global__ __launch_bounds__(256)
void pos_kernel() {
    extern __shared__ float sm[];
    float* rel_s = sm;                // 64*204
    float* qt    = sm + 64*204;       // 64*65
    int tid = threadIdx.x;
    int c  = blockIdx.y;
    int j0 = blockIdx.x * 64;
    for (int idx = tid; idx < Cc*DHd; idx += 256) {
        int r = idx >> 6, d = idx & 63;
        rel_s[d*204 + r] = g_rel[((size_t)c*Cc + r)*DHd + d];
    }
    for (int idx = tid; idx < 64*64; idx += 256) {
        int jj = idx >> 6, d = idx & 63;
        int j = j0 + jj;
        int b = j / (NBb*Hh), m = (j / Hh) % NBb, h = j & 7;
        qt[d*65 + jj] = g_q[(size_t)(b*Tt + m*Cc + c)*DIMN + h*DHd + d];
    }
    __syncthreads();
    int rt = tid & 31, ty = tid >> 5;
    #pragma unroll
    for (int pass = 0; pass < 2; pass++) {
        int rb = pass * 128;
        float acc[4][8];
        #pragma unroll
        for (int i = 0; i < 4; i++)
            #pragma unroll
            for (int jj = 0; jj < 8; jj++) acc[i][jj] = 0.f;
        #pragma unroll 4
        for (int k = 0; k < 64; k++) {
            float4 rv = *(const float4*)&rel_s[k*204 + rb + rt*4];
            #pragma unroll
            for (int jj = 0; jj < 8; jj++) {
                float qv = qt[k*65 + ty*8 + jj];
                acc[0][jj] += rv.x*qv; acc[1][jj] += rv.y*qv;
                acc[2][jj] += rv.z*qv; acc[3][jj] += rv.w*qv;
            }
        }
        if (pass == 0 || rt < 18) {
            #pragma unroll
            for (int jj = 0; jj < 8; jj++) {
                int j = j0 + ty*8 + jj;
                float4 o = make_float4(acc[0][jj]*SCALE, acc[1][jj]*SCALE,
                                       acc[2][jj]*SCALE, acc[3][jj]*SCALE);
                *(float4*)&g_pos[((size_t)j*Cc + c)*Cc + rb + rt*4] = o;
            }
        }
    }
}

// ---------------- tensor-core attention ----------------
// grid (4 q-tiles, NJ). 256 thr, 8 warps (4m x 2n).
// SMEM floats: Ks[208][68] | Vst[64][228] | U[64][228] (Vrm / Qs / Ps) | red[2][2][64]
#define KS_OFF  0
#define VST_OFF 14144
#define U_OFF   28736
#define RED_OFF 43328
#define ATTN_SMEM (43584*4)

__global__ __launch_bounds__(256)
void attn_mma() {
    extern __shared__ float sm[];
    float* Ks  = sm + KS_OFF;
    float* Vst = sm + VST_OFF;
    float* U   = sm + U_OFF;
    float* red = sm + RED_OFF;

    int tid = threadIdx.x, lane = tid & 31, warp = tid >> 5;
    int wm = warp >> 1, wn = warp & 1;
    int g = lane >> 2, t = lane & 3;
    int c0 = blockIdx.x * 64;
    int j  = blockIdx.y;
    int b = j / (NBb*Hh), m = (j / Hh) % NBb, h = j & 7;
    int t0 = b*Tt + m*Cc;
    const float* kvb = g_kv + (size_t)t0*(2*DIMN) + h*DHd;

    // K rows (tf32-rounded), zero-pad r in [200,208)
    for (int i4 = tid; i4 < 208*16; i4 += 256) {
        int r = i4 >> 4, d4 = (i4 & 15) * 4;
        float4 v = make_float4(0.f,0.f,0.f,0.f);
        if (r < Cc) v = *(const float4*)(kvb + (size_t)r*(2*DIMN) + d4);
        float* p = &Ks[r*68 + d4];
        p[0]=ftf(v.x); p[1]=ftf(v.y); p[2]=ftf(v.z); p[3]=ftf(v.w);
    }
    // V rows into U (row-major staging, stride 67)
    for (int i4 = tid; i4 < 200*16; i4 += 256) {
        int r = i4 >> 4, d4 = (i4 & 15) * 4;
        float4 v = *(const float4*)(kvb + (size_t)r*(2*DIMN) + DIMN + d4);
        float* p = &U[r*67 + d4];
        p[0]=ftf(v.x); p[1]=ftf(v.y); p[2]=ftf(v.z); p[3]=ftf(v.w);
    }
    __syncthreads();
    // transpose V: Vst[d][r], zero r>=200
    for (int d = warp; d < 64; d += 8)
        for (int r = lane; r < 208; r += 32)
            Vst[d*228 + r] = (r < Cc) ? U[r*67 + d] : 0.f;
    __syncthreads();
    // Q tile into U (stride 68), zero invalid rows
    for (int i4 = tid; i4 < 64*16; i4 += 256) {
        int mr = i4 >> 4, d4 = (i4 & 15) * 4;
        int c = c0 + mr;
        float4 v = make_float4(0.f,0.f,0.f,0.f);
        if (c < Cc) v = *(const float4*)(g_q + (size_t)(t0 + c)*DIMN + h*DHd + d4);
        float* p = &U[mr*68 + d4];
        p[0]=ftf(v.x); p[1]=ftf(v.y); p[2]=ftf(v.z); p[3]=ftf(v.w);
    }
    __syncthreads();

    // ---- S = Q K^T : warp tile 16 x 104 (13 n8 tiles) ----
    float sacc[13][4];
    #pragma unroll
    for (int nt = 0; nt < 13; nt++)
        #pragma unroll
        for (int i = 0; i < 4; i++) sacc[nt][i] = 0.f;

    int arow = (wm*16 + g)*68;
    #pragma unroll
    for (int k0 = 0; k0 < 64; k0 += 8) {
        int kk = k0 + t;
        unsigned A[4];
        A[0] = __float_as_uint(U[arow + kk]);
        A[1] = __float_as_uint(U[arow + 8*68 + kk]);
        A[2] = __float_as_uint(U[arow + kk + 4]);
        A[3] = __float_as_uint(U[arow + 8*68 + kk + 4]);
        #pragma unroll
        for (int nt = 0; nt < 13; nt++) {
            int n = wn*104 + nt*8 + g;
            unsigned Bf[2];
            Bf[0] = __float_as_uint(Ks[n*68 + kk]);
            Bf[1] = __float_as_uint(Ks[n*68 + kk + 4]);
            mma8(sacc[nt], A, Bf);
        }
    }

    // ---- pos bias + mask + softmax ----
    int r0 = wm*16 + g, r1 = r0 + 8;
    int cg0 = c0 + r0, cg1 = c0 + r1;
    const float* posb0 = g_pos + ((size_t)j*Cc + (cg0 < Cc ? cg0 : Cc-1))*Cc;
    const float* posb1 = g_pos + ((size_t)j*Cc + (cg1 < Cc ? cg1 : Cc-1))*Cc;
    float mx0 = -1e30f, mx1 = -1e30f;
    #pragma unroll
    for (int nt = 0; nt < 13; nt++) {
        int col = wn*104 + nt*8 + 2*t;
        if (col < Cc) {
            float2 p0 = *(const float2*)(posb0 + col);
            float2 p1 = *(const float2*)(posb1 + col);
            sacc[nt][0] = sacc[nt][0]*SCALE + p0.x;
            sacc[nt][1] = sacc[nt][1]*SCALE + p0.y;
            sacc[nt][2] = sacc[nt][2]*SCALE + p1.x;
            sacc[nt][3] = sacc[nt][3]*SCALE + p1.y;
        } else {
            sacc[nt][0] = sacc[nt][1] = sacc[nt][2] = sacc[nt][3] = -1e30f;
        }
        mx0 = fmaxf(mx0, fmaxf(sacc[nt][0], sacc[nt][1]));
        mx1 = fmaxf(mx1, fmaxf(sacc[nt][2], sacc[nt][3]));
    }
    #pragma unroll
    for (int o = 1; o <= 2; o <<= 1) {
        mx0 = fmaxf(mx0, __shfl_xor_sync(~0u, mx0, o));
        mx1 = fmaxf(mx1, __shfl_xor_sync(~0u, mx1, o));
    }
    if (t == 0) { red[wn*64 + r0] = mx0; red[wn*64 + r1] = mx1; }
    __syncthreads();
    mx0 = fmaxf(red[r0], red[64 + r0]);
    mx1 = fmaxf(red[r1], red[64 + r1]);

    float s0 = 0.f, s1 = 0.f;
    #pragma unroll
    for (int nt = 0; nt < 13; nt++) {
        sacc[nt][0] = __expf(sacc[nt][0] - mx0);
        sacc[nt][1] = __expf(sacc[nt][1] - mx0);
        sacc[nt][2] = __expf(sacc[nt][2] - mx1);
        sacc[nt][3] = __expf(sacc[nt][3] - mx1);
        s0 += sacc[nt][0] + sacc[nt][1];
        s1 += sacc[nt][2] + sacc[nt][3];
    }
    #pragma unroll
    for (int o = 1; o <= 2; o <<= 1) {
        s0 += __shfl_xor_sync(~0u, s0, o);
        s1 += __shfl_xor_sync(~0u, s1, o);
    }
    if (t == 0) { red[128 + wn*64 + r0] = s0; red[128 + wn*64 + r1] = s1; }
    // store unnormalized P (tf32) into U; sync also makes Q->P aliasing safe
    #pragma unroll
    for (int nt = 0; nt < 13; nt++) {
        int col = wn*104 + nt*8 + 2*t;
        *(float2*)&U[r0*228 + col] = make_float2(ftf(sacc[nt][0]), ftf(sacc[nt][1]));
        *(float2*)&U[r1*228 + col] = make_float2(ftf(sacc[nt][2]), ftf(sacc[nt][3]));
    }
    __syncthreads();
    float inv0 = 1.f / (red[128 + r0] + red[128 + 64 + r0]);
    float inv1 = 1.f / (red[128 + r1] + red[128 + 64 + r1]);

    // ---- O = P V : warp tile 16 x 32 (4 n8 tiles), k = 208 ----
    float oacc[4][4];
    #pragma unroll
    for (int nt = 0; nt < 4; nt++)
        #pragma unroll
        for (int i = 0; i < 4; i++) oacc[nt][i] = 0.f;

    int prow = (wm*16 + g)*228;
    #pragma unroll
    for (int k0 = 0; k0 < 208; k0 += 8) {
        int kk = k0 + t;
        unsigned A[4];
        A[0] = __float_as_uint(U[prow + kk]);
        A[1] = __float_as_uint(U[prow + 8*228 + kk]);
        A[2] = __float_as_uint(U[prow + kk + 4]);
        A[3] = __float_as_uint(U[prow + 8*228 + kk + 4]);
        #pragma unroll
        for (int nt = 0; nt < 4; nt++) {
            int n = wn*32 + nt*8 + g;
            unsigned Bf[2];
            Bf[0] = __float_as_uint(Vst[n*228 + kk]);
            Bf[1] = __float_as_uint(Vst[n*228 + kk + 4]);
            mma8(oacc[nt], A, Bf);
        }
    }

    float* ob = g_att + (size_t)t0*DIMN + h*DHd;
    #pragma unroll
    for (int nt = 0; nt < 4; nt++) {
        int d0 = wn*32 + nt*8 + 2*t;
        if (cg0 < Cc)
            *(float2*)(ob + (size_t)cg0*DIMN + d0) =
                make_float2(ftf(oacc[nt][0]*inv0), ftf(oacc[nt][1]*inv0));
        if (cg1 < Cc)
            *(float2*)(ob + (size_t)cg1*DIMN + d0) =
                make_float2(ftf(oacc[nt][2]*inv1), ftf(oacc[nt][3]*inv1));
    }
}

// ---------------- launch ----------------
extern "C" void kernel_launch(void* const* d_in, const int* in_sizes, int n_in,
                              void* d_out, int out_size) {
    const float* x    = (const float*)d_in[0];
    const int*   dst  = (const int*)  d_in[1];
    const float* lng  = (const float*)d_in[2];
    const float* lnb  = (const float*)d_in[3];
    const float* Wq   = (const float*)d_in[4];
    const float* Wkv  = (const float*)d_in[5];
    const float* pe   = (const float*)d_in[6];
    const float* Wo   = (const float*)d_in[7];
    const float* bo   = (const float*)d_in[8];
    float* out = (float*)d_out;

    void* tmp;
    cudaGetSymbolAddress(&tmp, g_xn);  float* xn  = (float*)tmp;
    cudaGetSymbolAddress(&tmp, g_q);   float* q   = (float*)tmp;
    cudaGetSymbolAddress(&tmp, g_kv);  float* kv  = (float*)tmp;
    cudaGetSymbolAddress(&tmp, g_att); float* att = (float*)tmp;
    cudaGetSymbolAddress(&tmp, g_wq);  float* wq  = (float*)tmp;
    cudaGetSymbolAddress(&tmp, g_wkv); float* wkv = (float*)tmp;
    cudaGetSymbolAddress(&tmp, g_wo);  float* wo  = (float*)tmp;

    cudaFuncSetAttribute(pos_kernel, cudaFuncAttributeMaxDynamicSharedMemorySize, 68864);
    cudaFuncSetAttribute(attn_mma,   cudaFuncAttributeMaxDynamicSharedMemorySize, ATTN_SMEM);

    round_kernel<<<(DIMN*DIMN/4 + 255)/256, 256>>>(Wq,  wq,  DIMN*DIMN/4);
    round_kernel<<<(DIMN*2*DIMN/4 + 255)/256, 256>>>(Wkv, wkv, DIMN*2*DIMN/4);
    round_kernel<<<(DIMN*DIMN/4 + 255)/256, 256>>>(Wo,  wo,  DIMN*DIMN/4);

    ln_kernel<<<Mm, 128>>>(x, lng, lnb);
    gather_kernel<<<(Cc*Cc*DHd + 255)/256, 256>>>(dst, pe);
    gemm_tf32<<<dim3(DIMN/BN,   Mm/BM), 256>>>(xn, wq,  nullptr, q,  DIMN);
    gemm_tf32<<<dim3(2*DIMN/BN, Mm/BM), 256>>>(xn, wkv, nullptr, kv, 2*DIMN);
    pos_kernel<<<dim3(NJ/64, Cc), 256, 68864>>>();
    attn_mma<<<dim3(4, NJ), 256, ATTN_SMEM>>>();
    gemm_tf32<<<dim3(DIMN/BN, Mm/BM), 256>>>(att, wo, bo, out, DIMN);
}

// round 4
// speedup vs baseline: 1.3314x; 1.3314x over previous
#include <cuda_runtime.h>
#include <math.h>

// ---------------- problem constants ----------------
#define Bb   4
#define Tt   8000
#define DIMN 512
#define Hh   8
#define DHd  64
#define Cc   200
#define NBb  40
#define Mm   (Bb*Tt)        // 32000
#define NJ   (Bb*NBb*Hh)    // 1280
#define SCALE 0.125f

// ---------------- scratch (device globals; no allocation allowed) ----------------
__device__ float g_xn [Mm*DIMN];
__device__ float g_q  [Mm*DIMN];
__device__ float g_kv [Mm*2*DIMN];
__device__ float g_rel[Cc*Cc*DHd];
__device__ float g_pos[(size_t)NJ*Cc*Cc];   // [j][c][r], scaled, compact
__device__ float g_att[Mm*DIMN];
__device__ float g_wq [DIMN*DIMN];
__device__ float g_wkv[DIMN*2*DIMN];
__device__ float g_wo [DIMN*DIMN];

__device__ __forceinline__ unsigned f2tf32(float f) {
    unsigned u; asm("cvt.rna.tf32.f32 %0, %1;" : "=r"(u) : "f"(f)); return u;
}
__device__ __forceinline__ float ftf(float f) { return __uint_as_float(f2tf32(f)); }

// ---------------- pre-round weights to tf32 bit-pattern ----------------
__global__ void round_kernel(const float* __restrict__ src, float* __restrict__ dst, int n4) {
    int i = blockIdx.x*256 + threadIdx.x;
    if (i < n4) {
        float4 v = ((const float4*)src)[i];
        uint4 o = make_uint4(f2tf32(v.x), f2tf32(v.y), f2tf32(v.z), f2tf32(v.w));
        ((uint4*)dst)[i] = o;
    }
}

// ---------------- LayerNorm: one block per row (stores tf32-rounded) ----------------
__global__ void ln_kernel(const float* __restrict__ x,
                          const float* __restrict__ g,
                          const float* __restrict__ bta) {
    int row = blockIdx.x;
    int t = threadIdx.x;
    float4 v = ((const float4*)(x + (size_t)row*DIMN))[t];
    float s  = v.x + v.y + v.z + v.w;
    float ss = v.x*v.x + v.y*v.y + v.z*v.z + v.w*v.w;
    #pragma unroll
    for (int o = 16; o; o >>= 1) {
        s  += __shfl_xor_sync(~0u, s,  o);
        ss += __shfl_xor_sync(~0u, ss, o);
    }
    __shared__ float rs[4], rss[4];
    int w = t >> 5;
    if ((t & 31) == 0) { rs[w] = s; rss[w] = ss; }
    __syncthreads();
    s  = rs[0]  + rs[1]  + rs[2]  + rs[3];
    ss = rss[0] + rss[1] + rss[2] + rss[3];
    float mu  = s  * (1.0f/DIMN);
    float var = ss * (1.0f/DIMN) - mu*mu;
    float inv = rsqrtf(var + 1e-5f);
    float4 gg = ((const float4*)g)[t];
    float4 bb = ((const float4*)bta)[t];
    uint4 o;
    o.x = f2tf32((v.x-mu)*inv*gg.x + bb.x);
    o.y = f2tf32((v.y-mu)*inv*gg.y + bb.y);
    o.z = f2tf32((v.z-mu)*inv*gg.z + bb.z);
    o.w = f2tf32((v.w-mu)*inv*gg.w + bb.w);
    ((uint4*)(g_xn + (size_t)row*DIMN))[t] = o;
}

// ---------------- rel gather (tf32-rounded, used only by pos_mma) ----------------
__global__ void gather_kernel(const int* __restrict__ dists,
                              const float* __restrict__ pe) {
    int idx = blockIdx.x*256 + threadIdx.x;
    if (idx < Cc*Cc*DHd) {
        int cr = idx >> 6, d = idx & 63;
        g_rel[idx] = ftf(pe[dists[cr]*DHd + d]);
    }
}

// ---------------- mma helper ----------------
__device__ __forceinline__ void mma8(float* c, const unsigned* a, const unsigned* b) {
    asm volatile("mma.sync.aligned.m16n8k8.row.col.f32.tf32.tf32.f32 "
        "{%0,%1,%2,%3}, {%4,%5,%6,%7}, {%8,%9}, {%0,%1,%2,%3};"
        : "+f"(c[0]), "+f"(c[1]), "+f"(c[2]), "+f"(c[3])
        : "r"(a[0]), "r"(a[1]), "r"(a[2]), "r"(a[3]), "r"(b[0]), "r"(b[1]));
}

// ---------------- tf32 tensor-core GEMM (unchanged) ----------------
#define BM 128
#define BN 128
#define BK 16
#define AST 136

__global__ __launch_bounds__(256)
void gemm_tf32(const float* __restrict__ A, const float* __restrict__ W,
               const float* __restrict__ bias, float* __restrict__ out, int N) {
    __shared__ unsigned As[2][BK][AST];
    __shared__ unsigned Bs[2][BK][AST];
    int tid  = threadIdx.x;
    int lane = tid & 31, warp = tid >> 5;
    int wm = warp >> 2, wn = warp & 3;
    int m0 = blockIdx.y*BM, n0 = blockIdx.x*BN;

    int ar = tid >> 2;
    int ak = (tid & 3) * 4;
    int ag = tid & 3;
    int bk = tid >> 4;
    int bn = (tid & 15) * 4;

    const float* Aptr = A + (size_t)(m0 + ar)*DIMN + ak;
    const float* Wptr = W + (size_t)bk*N + n0 + bn;

    float acc[4][4][4];
    #pragma unroll
    for (int i=0;i<4;i++)
        #pragma unroll
        for (int j=0;j<4;j++)
            #pragma unroll
            for (int r=0;r<4;r++) acc[i][j][r]=0.f;

    {
        float4 a0v = *(const float4*)(Aptr);
        float4 a1v = *(const float4*)(Aptr + (size_t)64*DIMN);
        unsigned d0 = (unsigned)__cvta_generic_to_shared(&Bs[0][bk][bn]);
        unsigned d1 = (unsigned)__cvta_generic_to_shared(&Bs[0][bk][bn+64]);
        asm volatile("cp.async.cg.shared.global [%0], [%1], 16;" :: "r"(d0), "l"(Wptr));
        asm volatile("cp.async.cg.shared.global [%0], [%1], 16;" :: "r"(d1), "l"(Wptr+64));
        asm volatile("cp.async.commit_group;");
        int c0 = ar ^ (ag<<3), c1 = (ar+64) ^ (ag<<3);
        As[0][ak+0][c0]=__float_as_uint(a0v.x); As[0][ak+1][c0]=__float_as_uint(a0v.y);
        As[0][ak+2][c0]=__float_as_uint(a0v.z); As[0][ak+3][c0]=__float_as_uint(a0v.w);
        As[0][ak+0][c1]=__float_as_uint(a1v.x); As[0][ak+1][c1]=__float_as_uint(a1v.y);
        As[0][ak+2][c1]=__float_as_uint(a1v.z); As[0][ak+3][c1]=__float_as_uint(a1v.w);
        asm volatile("cp.async.wait_group 0;");
        __syncthreads();
    }

    int buf = 0;
    for (int k0 = BK; k0 <= DIMN; k0 += BK) {
        float4 a0v, a1v;
        if (k0 < DIMN) {
            a0v = *(const float4*)(Aptr + k0);
            a1v = *(const float4*)(Aptr + (size_t)64*DIMN + k0);
            unsigned d0 = (unsigned)__cvta_generic_to_shared(&Bs[buf^1][bk][bn]);
            unsigned d1 = (unsigned)__cvta_generic_to_shared(&Bs[buf^1][bk][bn+64]);
            const float* wp = Wptr + (size_t)k0*N;
            asm volatile("cp.async.cg.shared.global [%0], [%1], 16;" :: "r"(d0), "l"(wp));
            asm volatile("cp.async.cg.shared.global [%0], [%1], 16;" :: "r"(d1), "l"(wp+64));
            asm volatile("cp.async.commit_group;");
        }
        #pragma unroll
        for (int ks = 0; ks < 2; ks++) {
            unsigned af[4][4], bf[4][2];
            int kr = ks*8 + (lane & 3);
            int g0 = (2*ks) << 3, g1 = (2*ks+1) << 3;
            #pragma unroll
            for (int mt = 0; mt < 4; mt++) {
                int mb = wm*64 + mt*16 + (lane>>2);
                af[mt][0] = As[buf][kr  ][ mb    ^ g0];
                af[mt][1] = As[buf][kr  ][(mb+8) ^ g0];
                af[mt][2] = As[buf][kr+4][ mb    ^ g1];
                af[mt][3] = As[buf][kr+4][(mb+8) ^ g1];
            }
            #pragma unroll
            for (int nt = 0; nt < 4; nt++) {
                int nb = wn*32 + nt*8 + (lane>>2);
                bf[nt][0] = Bs[buf][kr  ][nb];
                bf[nt][1] = Bs[buf][kr+4][nb];
            }
            #pragma unroll
            for (int mt = 0; mt < 4; mt++)
                #pragma unroll
                for (int nt = 0; nt < 4; nt++)
                    mma8(acc[mt][nt], af[mt], bf[nt]);
        }
        if (k0 < DIMN) {
            int c0 = ar ^ (ag<<3), c1 = (ar+64) ^ (ag<<3);
            As[buf^1][ak+0][c0]=__float_as_uint(a0v.x); As[buf^1][ak+1][c0]=__float_as_uint(a0v.y);
            As[buf^1][ak+2][c0]=__float_as_uint(a0v.z); As[buf^1][ak+3][c0]=__float_as_uint(a0v.w);
            As[buf^1][ak+0][c1]=__float_as_uint(a1v.x); As[buf^1][ak+1][c1]=__float_as_uint(a1v.y);
            As[buf^1][ak+2][c1]=__float_as_uint(a1v.z); As[buf^1][ak+3][c1]=__float_as_uint(a1v.w);
            asm volatile("cp.async.wait_group 0;");
            __syncthreads();
            buf ^= 1;
        }
    }

    #pragma unroll
    for (int mt = 0; mt < 4; mt++) {
        int row = m0 + wm*64 + mt*16 + (lane>>2);
        #pragma unroll
        for (int nt = 0; nt < 4; nt++) {
            int col = n0 + wn*32 + nt*8 + (lane&3)*2;
            float bv0 = 0.f, bv1 = 0.f;
            if (bias) { bv0 = bias[col]; bv1 = bias[col+1]; }
            *(float2*)(out + (size_t)row*N + col) =
                make_float2(acc[mt][nt][0]+bv0, acc[mt][nt][1]+bv1);
            *(float2*)(out + (size_t)(row+8)*N + col) =
                make_float2(acc[mt][nt][2]+bv0, acc[mt][nt][3]+bv1);
        }
    }
}

// ---------------- pos bias via MMA: P[j][c][r] = SCALE * q_c[j] . rel[c][r] ----------------
// grid (NJ/64, Cc). 256 thr, 8 warps (4m x 2n). M=64 j, N=208 r (pad), K=64.
// SMEM: Qs[64][68] + Rs[208][68] = 73,984 B
#define PM_SMEM ((64*68 + 208*68)*4)
__global__ __launch_bounds__(256)
void pos_mma() {
    extern __shared__ float sm[];
    float* Qs = sm;             // 64 x 68
    float* Rs = sm + 64*68;     // 208 x 68
    int tid = threadIdx.x, lane = tid & 31, warp = tid >> 5;
    int wm = warp >> 1, wn = warp & 1;
    int g = lane >> 2, t = lane & 3;
    int c  = blockIdx.y;
    int j0 = blockIdx.x * 64;

    // rel[c] rows (already tf32), zero-pad r in [200,208)
    for (int i4 = tid; i4 < 208*16; i4 += 256) {
        int r = i4 >> 4, d4 = (i4 & 15) * 4;
        float4 v = make_float4(0.f,0.f,0.f,0.f);
        if (r < Cc) v = *(const float4*)(g_rel + ((size_t)c*Cc + r)*DHd + d4);
        float* p = &Rs[r*68 + d4];
        p[0]=v.x; p[1]=v.y; p[2]=v.z; p[3]=v.w;
    }
    // q rows for this c, j-tile (tf32-round at store)
    for (int i4 = tid; i4 < 64*16; i4 += 256) {
        int jj = i4 >> 4, d4 = (i4 & 15) * 4;
        int j = j0 + jj;
        int bm = j >> 3, h = j & 7;
        int b = bm / NBb, mB = bm % NBb;
        float4 v = *(const float4*)(g_q + (size_t)(b*Tt + mB*Cc + c)*DIMN + h*DHd + d4);
        float* p = &Qs[jj*68 + d4];
        p[0]=ftf(v.x); p[1]=ftf(v.y); p[2]=ftf(v.z); p[3]=ftf(v.w);
    }
    __syncthreads();

    float acc[13][4];
    #pragma unroll
    for (int nt = 0; nt < 13; nt++)
        #pragma unroll
        for (int i = 0; i < 4; i++) acc[nt][i] = 0.f;

    int arow = (wm*16 + g)*68;
    #pragma unroll
    for (int k0 = 0; k0 < 64; k0 += 8) {
        int kk = k0 + t;
        unsigned A[4];
        A[0] = __float_as_uint(Qs[arow + kk]);
        A[1] = __float_as_uint(Qs[arow + 8*68 + kk]);
        A[2] = __float_as_uint(Qs[arow + kk + 4]);
        A[3] = __float_as_uint(Qs[arow + 8*68 + kk + 4]);
        #pragma unroll
        for (int nt = 0; nt < 13; nt++) {
            int n = wn*104 + nt*8 + g;
            unsigned B[2];
            B[0] = __float_as_uint(Rs[n*68 + kk]);
            B[1] = __float_as_uint(Rs[n*68 + kk + 4]);
            mma8(acc[nt], A, B);
        }
    }

    size_t jm0 = j0 + wm*16 + g, jm1 = jm0 + 8;
    #pragma unroll
    for (int nt = 0; nt < 13; nt++) {
        int col = wn*104 + nt*8 + 2*t;
        if (col < Cc - 1) {
            *(float2*)&g_pos[(jm0*Cc + c)*Cc + col] =
                make_float2(acc[nt][0]*SCALE, acc[nt][1]*SCALE);
            *(float2*)&g_pos[(jm1*Cc + c)*Cc + col] =
                make_float2(acc[nt][2]*SCALE, acc[nt][3]*SCALE);
        }
    }
}

// ---------------- tensor-core attention v2: warp-independent rows ----------------
// grid (2, NJ). 256 thr, 8 warps; warp w owns query rows [16w, 16w+16).
// SMEM floats: Ks[208][68] | Vst[64][212] | U[128][212] (V-staging / Q / P)
#define KS_OFF  0
#define VST_OFF 14144
#define U_OFF   27712
#define ATTN_SMEM (54848*4)

__global__ __launch_bounds__(256)
void attn_mma() {
    extern __shared__ float sm[];
    float* Ks  = sm + KS_OFF;
    float* Vst = sm + VST_OFF;
    float* U   = sm + U_OFF;

    int tid = threadIdx.x, lane = tid & 31, warp = tid >> 5;
    int g = lane >> 2, t = lane & 3;
    int c0 = blockIdx.x * 128;
    int j  = blockIdx.y;
    int b = j / (NBb*Hh), mB = (j / Hh) % NBb, h = j & 7;
    int t0 = b*Tt + mB*Cc;
    const float* kvb = g_kv + (size_t)t0*(2*DIMN) + h*DHd;

    // K rows (tf32), zero-pad r in [200,208)
    for (int i4 = tid; i4 < 208*16; i4 += 256) {
        int r = i4 >> 4, d4 = (i4 & 15) * 4;
        float4 v = make_float4(0.f,0.f,0.f,0.f);
        if (r < Cc) v = *(const float4*)(kvb + (size_t)r*(2*DIMN) + d4);
        float* p = &Ks[r*68 + d4];
        p[0]=ftf(v.x); p[1]=ftf(v.y); p[2]=ftf(v.z); p[3]=ftf(v.w);
    }
    // V rows into U staging (stride 67)
    for (int i4 = tid; i4 < 200*16; i4 += 256) {
        int r = i4 >> 4, d4 = (i4 & 15) * 4;
        float4 v = *(const float4*)(kvb + (size_t)r*(2*DIMN) + DIMN + d4);
        float* p = &U[r*67 + d4];
        p[0]=ftf(v.x); p[1]=ftf(v.y); p[2]=ftf(v.z); p[3]=ftf(v.w);
    }
    __syncthreads();
    // transpose V -> Vst[d][r], zero r>=200
    for (int d = warp; d < 64; d += 8)
        for (int r = lane; r < 208; r += 32)
            Vst[d*212 + r] = (r < Cc) ? U[r*67 + d] : 0.f;
    __syncthreads();
    // Q rows (stride 212), zero rows with c >= 200
    for (int i4 = tid; i4 < 128*16; i4 += 256) {
        int mr = i4 >> 4, d4 = (i4 & 15) * 4;
        int c = c0 + mr;
        float4 v = make_float4(0.f,0.f,0.f,0.f);
        if (c < Cc) v = *(const float4*)(g_q + (size_t)(t0 + c)*DIMN + h*DHd + d4);
        float* p = &U[mr*212 + d4];
        p[0]=ftf(v.x); p[1]=ftf(v.y); p[2]=ftf(v.z); p[3]=ftf(v.w);
    }
    __syncthreads();

    // ---- S = Q K^T : warp rows (16w+g, +8), all 208 cols (26 n8 tiles) ----
    int row = warp*16 + g;
    float sacc[26][4];
    #pragma unroll
    for (int nt = 0; nt < 26; nt++)
        #pragma unroll
        for (int i = 0; i < 4; i++) sacc[nt][i] = 0.f;

    #pragma unroll
    for (int k0 = 0; k0 < 64; k0 += 8) {
        int kk = k0 + t;
        unsigned A[4];
        A[0] = __float_as_uint(U[row*212 + kk]);
        A[1] = __float_as_uint(U[(row+8)*212 + kk]);
        A[2] = __float_as_uint(U[row*212 + kk + 4]);
        A[3] = __float_as_uint(U[(row+8)*212 + kk + 4]);
        #pragma unroll
        for (int nt = 0; nt < 26; nt++) {
            int n = nt*8 + g;
            unsigned B[2];
            B[0] = __float_as_uint(Ks[n*68 + kk]);
            B[1] = __float_as_uint(Ks[n*68 + kk + 4]);
            mma8(sacc[nt], A, B);
        }
    }

    // ---- pos bias + mask + warp-local softmax ----
    int cg0 = c0 + row, cg1 = cg0 + 8;
    const float* p0 = g_pos + ((size_t)j*Cc + (cg0 < Cc ? cg0 : Cc-1))*Cc;
    const float* p1 = g_pos + ((size_t)j*Cc + (cg1 < Cc ? cg1 : Cc-1))*Cc;
    float mx0 = -1e30f, mx1 = -1e30f;
    #pragma unroll
    for (int nt = 0; nt < 26; nt++) {
        int col = nt*8 + 2*t;
        if (col < Cc) {
            float2 b0 = *(const float2*)(p0 + col);
            float2 b1 = *(const float2*)(p1 + col);
            sacc[nt][0] = sacc[nt][0]*SCALE + b0.x;
            sacc[nt][1] = sacc[nt][1]*SCALE + b0.y;
            sacc[nt][2] = sacc[nt][2]*SCALE + b1.x;
            sacc[nt][3] = sacc[nt][3]*SCALE + b1.y;
        } else {
            sacc[nt][0] = sacc[nt][1] = sacc[nt][2] = sacc[nt][3] = -1e30f;
        }
        mx0 = fmaxf(mx0, fmaxf(sacc[nt][0], sacc[nt][1]));
        mx1 = fmaxf(mx1, fmaxf(sacc[nt][2], sacc[nt][3]));
    }
    #pragma unroll
    for (int o = 1; o <= 2; o <<= 1) {
        mx0 = fmaxf(mx0, __shfl_xor_sync(~0u, mx0, o));
        mx1 = fmaxf(mx1, __shfl_xor_sync(~0u, mx1, o));
    }
    float s0 = 0.f, s1 = 0.f;
    #pragma unroll
    for (int nt = 0; nt < 26; nt++) {
        sacc[nt][0] = __expf(sacc[nt][0] - mx0);
        sacc[nt][1] = __expf(sacc[nt][1] - mx0);
        sacc[nt][2] = __expf(sacc[nt][2] - mx1);
        sacc[nt][3] = __expf(sacc[nt][3] - mx1);
        s0 += sacc[nt][0] + sacc[nt][1];
        s1 += sacc[nt][2] + sacc[nt][3];
    }
    #pragma unroll
    for (int o = 1; o <= 2; o <<= 1) {
        s0 += __shfl_xor_sync(~0u, s0, o);
        s1 += __shfl_xor_sync(~0u, s1, o);
    }
    float inv0 = 1.f / s0, inv1 = 1.f / s1;

    // store unnormalized P (tf32) over own Q rows — warp-local, no block sync
    #pragma unroll
    for (int nt = 0; nt < 26; nt++) {
        int col = nt*8 + 2*t;
        *(float2*)&U[row*212 + col]     = make_float2(ftf(sacc[nt][0]), ftf(sacc[nt][1]));
        *(float2*)&U[(row+8)*212 + col] = make_float2(ftf(sacc[nt][2]), ftf(sacc[nt][3]));
    }
    __syncwarp();

    // ---- O = P V : 8 n8 tiles, k = 208 ----
    float oacc[8][4];
    #pragma unroll
    for (int nt = 0; nt < 8; nt++)
        #pragma unroll
        for (int i = 0; i < 4; i++) oacc[nt][i] = 0.f;

    #pragma unroll
    for (int k0 = 0; k0 < 208; k0 += 8) {
        int kk = k0 + t;
        unsigned A[4];
        A[0] = __float_as_uint(U[row*212 + kk]);
        A[1] = __float_as_uint(U[(row+8)*212 + kk]);
        A[2] = __float_as_uint(U[row*212 + kk + 4]);
        A[3] = __float_as_uint(U[(row+8)*212 + kk + 4]);
        #pragma unroll
        for (int nt = 0; nt < 8; nt++) {
            int n = nt*8 + g;
            unsigned B[2];
            B[0] = __float_as_uint(Vst[n*212 + kk]);
            B[1] = __float_as_uint(Vst[n*212 + kk + 4]);
            mma8(oacc[nt], A, B);
        }
    }

    float* ob = g_att + (size_t)t0*DIMN + h*DHd;
    #pragma unroll
    for (int nt = 0; nt < 8; nt++) {
        int d0 = nt*8 + 2*t;
        if (cg0 < Cc)
            *(float2*)(ob + (size_t)cg0*DIMN + d0) =
                make_float2(ftf(oacc[nt][0]*inv0), ftf(oacc[nt][1]*inv0));
        if (cg1 < Cc)
            *(float2*)(ob + (size_t)cg1*DIMN + d0) =
                make_float2(ftf(oacc[nt][2]*inv1), ftf(oacc[nt][3]*inv1));
    }
}

// ---------------- launch ----------------
extern "C" void kernel_launch(void* const* d_in, const int* in_sizes, int n_in,
                              void* d_out, int out_size) {
    const float* x    = (const float*)d_in[0];
    const int*   dst  = (const int*)  d_in[1];
    const float* lng  = (const float*)d_in[2];
    const float* lnb  = (const float*)d_in[3];
    const float* Wq   = (const float*)d_in[4];
    const float* Wkv  = (const float*)d_in[5];
    const float* pe   = (const float*)d_in[6];
    const float* Wo   = (const float*)d_in[7];
    const float* bo   = (const float*)d_in[8];
    float* out = (float*)d_out;

    void* tmp;
    cudaGetSymbolAddress(&tmp, g_xn);  float* xn  = (float*)tmp;
    cudaGetSymbolAddress(&tmp, g_q);   float* q   = (float*)tmp;
    cudaGetSymbolAddress(&tmp, g_kv);  float* kv  = (float*)tmp;
    cudaGetSymbolAddress(&tmp, g_att); float* att = (float*)tmp;
    cudaGetSymbolAddress(&tmp, g_wq);  float* wq  = (float*)tmp;
    cudaGetSymbolAddress(&tmp, g_wkv); float* wkv = (float*)tmp;
    cudaGetSymbolAddress(&tmp, g_wo);  float* wo  = (float*)tmp;

    cudaFuncSetAttribute(pos_mma,  cudaFuncAttributeMaxDynamicSharedMemorySize, PM_SMEM);
    cudaFuncSetAttribute(attn_mma, cudaFuncAttributeMaxDynamicSharedMemorySize, ATTN_SMEM);

    round_kernel<<<(DIMN*DIMN/4 + 255)/256, 256>>>(Wq,  wq,  DIMN*DIMN/4);
    round_kernel<<<(DIMN*2*DIMN/4 + 255)/256, 256>>>(Wkv, wkv, DIMN*2*DIMN/4);
    round_kernel<<<(DIMN*DIMN/4 + 255)/256, 256>>>(Wo,  wo,  DIMN*DIMN/4);

    ln_kernel<<<Mm, 128>>>(x, lng, lnb);
    gather_kernel<<<(Cc*Cc*DHd + 255)/256, 256>>>(dst, pe);
    gemm_tf32<<<dim3(DIMN/BN,   Mm/BM), 256>>>(xn, wq,  nullptr, q,  DIMN);
    gemm_tf32<<<dim3(2*DIMN/BN, Mm/BM), 256>>>(xn, wkv, nullptr, kv, 2*DIMN);
    pos_mma<<<dim3(NJ/64, Cc), 256, PM_SMEM>>>();
    attn_mma<<<dim3(2, NJ), 256, ATTN_SMEM>>>();
    gemm_tf32<<<dim3(DIMN/BN, Mm/BM), 256>>>(att, wo, bo, out, DIMN);
}